// round 13
// baseline (speedup 1.0000x reference)
#include <cuda_runtime.h>
#include <cuda_bf16.h>
#include <math.h>

#define NN 768
#define NPAIR (NN * NN)          // 589824
#define NJ 17
#define TILE_J 32                // j-tile per block
#define WARPS_PER_BLOCK 16       // 16 i-rows per block (512 threads)
#define NROWS (WARPS_PER_BLOCK + TILE_J)   // 48 vis_feat rows per block

// ---------------- helpers ----------------
__device__ __forceinline__ float4 mul4(float4 a, float4 b) {
    return make_float4(a.x * b.x, a.y * b.y, a.z * b.z, a.w * b.w);
}
__device__ __forceinline__ float dot4(float4 a, float4 b) {
    return fmaf(a.x, b.x, fmaf(a.y, b.y, fmaf(a.z, b.z, a.w * b.w)));
}

// ---------------- single fused kernel ----------------
__global__ void __launch_bounds__(WARPS_PER_BLOCK * 32, 2)
assoc_fused(const float* __restrict__ vm,     // [768, 32]
            const float* __restrict__ loc,    // [768, 5]
            const int*   __restrict__ cls,    // [768]
            const float* __restrict__ Wcu,    // [17, 128]
            const float* __restrict__ Wcv,    // [17, 128]
            const float* __restrict__ Wloc,   // [4, 128]
            const float* __restrict__ Wvis,   // [32, 128]
            const float* __restrict__ Wp,     // [384]
            float* __restrict__ out) {
    __shared__ float sT2[NJ * 128];           // relu(Wcv)
    __shared__ float s_vm[NROWS * 32];        // staged vis_maps rows
    __shared__ float s_vf[NROWS * 128];       // vis_feat rows (16 i then 32 j)
    __shared__ float s_nx[NROWS], s_ny[NROWS];
    __shared__ int   s_cls[NROWS];

    const int t  = threadIdx.x;               // 512
    const int nt = WARPS_PER_BLOCK * 32;
    const int i0 = blockIdx.x * WARPS_PER_BLOCK;
    const int j0 = blockIdx.y * TILE_J;

    // stage vis_maps rows + per-row scalars  (row r<16 -> i0+r, else j0+r-16)
    for (int idx = t; idx < NROWS * 32; idx += nt) {
        const int r = idx >> 5;
        const int g = (r < WARPS_PER_BLOCK) ? (i0 + r) : (j0 + r - WARPS_PER_BLOCK);
        s_vm[idx] = vm[g * 32 + (idx & 31)];
    }
    if (t < NROWS) {
        const int g = (t < WARPS_PER_BLOCK) ? (i0 + t) : (j0 + t - WARPS_PER_BLOCK);
        s_nx[t]  = loc[g * 5 + 3] * (1.0f / 48.0f);
        s_ny[t]  = loc[g * 5 + 4] * (1.0f / 64.0f);
        s_cls[t] = cls[g];
    }
    for (int idx = t; idx < NJ * 128; idx += nt)
        sT2[idx] = fmaxf(Wcv[idx], 0.0f);
    __syncthreads();

    // vis_feat rows: s_vf[r][c] = relu(sum_k s_vm[r][k] * Wvis[k][c])
    for (int idx = t; idx < NROWS * 128; idx += nt) {
        const int r = idx >> 7;
        const int c = idx & 127;
        float acc = 0.0f;
#pragma unroll
        for (int k = 0; k < 32; k++)
            acc = fmaf(s_vm[r * 32 + k], __ldg(&Wvis[k * 128 + c]), acc);
        s_vf[idx] = fmaxf(acc, 0.0f);
    }
    __syncthreads();

    const int warp = t >> 5;
    const int lane = t & 31;
    const int c4 = lane * 4;

    const int i = i0 + warp;

    // i-invariant registers
    const float4 vi  = *reinterpret_cast<const float4*>(&s_vf[warp * 128 + c4]);
    float4 f1 = *reinterpret_cast<const float4*>(&Wcu[s_cls[warp] * 128 + c4]);
    f1.x = fmaxf(f1.x, 0.0f); f1.y = fmaxf(f1.y, 0.0f);
    f1.z = fmaxf(f1.z, 0.0f); f1.w = fmaxf(f1.w, 0.0f);
    const float4 wpv = *reinterpret_cast<const float4*>(&Wp[c4]);
    const float4 wpc = *reinterpret_cast<const float4*>(&Wp[128 + c4]);
    const float4 wpg = *reinterpret_cast<const float4*>(&Wp[256 + c4]);
    const float4 wa  = *reinterpret_cast<const float4*>(&Wloc[c4]);
    const float4 wb  = *reinterpret_cast<const float4*>(&Wloc[128 + c4]);
    const float4 wc  = *reinterpret_cast<const float4*>(&Wloc[256 + c4]);
    const float4 wd  = *reinterpret_cast<const float4*>(&Wloc[384 + c4]);
    const float4 wl0 = make_float4(wa.x + wc.x, wa.y + wc.y, wa.z + wc.z, wa.w + wc.w);
    const float4 wl1 = make_float4(wb.x + wd.x, wb.y + wd.y, wb.z + wd.z, wb.w + wd.w);
    const float  nxi = s_nx[warp];
    const float  nyi = s_ny[warp];
    const bool   lo  = (lane < 16);

    float* __restrict__ ass = out;                        // [N, N]
    float* frow = out + (size_t)NPAIR + ((size_t)i * NN + j0) * 384;

    for (int jj = 0; jj < TILE_J; jj += 8) {
        float comb[4];   // one folded value per (j, j+1) pair
        float acc_prev;
#pragma unroll
        for (int q = 0; q < 8; q++) {
            const int rj = WARPS_PER_BLOCK + jj + q;
            const float4 vj = *reinterpret_cast<const float4*>(&s_vf[rj * 128 + c4]);
            const float4 f2 = *reinterpret_cast<const float4*>(&sT2[s_cls[rj] * 128 + c4]);
            const float dx = nxi - s_nx[rj];
            const float dy = nyi - s_ny[rj];
            const float g0 = dx * dx;
            const float g1 = dy * dy;

            const float4 v  = mul4(vi, vj);
            const float4 cl = mul4(f1, f2);
            float4 ge;
            ge.x = fmaxf(fmaf(g0, wl0.x, g1 * wl1.x), 0.0f);
            ge.y = fmaxf(fmaf(g0, wl0.y, g1 * wl1.y), 0.0f);
            ge.z = fmaxf(fmaf(g0, wl0.z, g1 * wl1.z), 0.0f);
            ge.w = fmaxf(fmaf(g0, wl0.w, g1 * wl1.w), 0.0f);

            float* p = frow + (size_t)(jj + q) * 384;
            __stcs(reinterpret_cast<float4*>(p + c4),       v);
            __stcs(reinterpret_cast<float4*>(p + 128 + c4), cl);
            __stcs(reinterpret_cast<float4*>(p + 256 + c4), ge);

            const float acc = dot4(v, wpv) + dot4(cl, wpc) + dot4(ge, wpg);
            if (q & 1) {
                // immediate pair fold: lanes 0-15 carry j(q-1), 16-31 carry j(q)
                comb[q >> 1] = (lo ? acc_prev : acc)
                             + __shfl_xor_sync(0xFFFFFFFFu, lo ? acc : acc_prev, 16);
            } else {
                acc_prev = acc;
            }
        }

        // finish four 16-lane reductions + stores
#pragma unroll
        for (int h = 0; h < 4; h++) {
            float cmb = comb[h];
#pragma unroll
            for (int off = 8; off; off >>= 1)
                cmb += __shfl_xor_sync(0xFFFFFFFFu, cmb, off);
            if ((lane & 15) == 0)
                __stcs(&ass[(size_t)i * NN + j0 + jj + 2 * h + (lane >> 4)],
                       1.0f / (1.0f + __expf(-cmb)));
        }
    }
}

// ---------------- launch ----------------
extern "C" void kernel_launch(void* const* d_in, const int* in_sizes, int n_in,
                              void* d_out, int out_size) {
    const float* vis_maps  = (const float*)d_in[0];  // [768, 32]
    const float* locations = (const float*)d_in[1];  // [768, 5]
    const int*   kpt_cls   = (const int*)d_in[2];    // [768]
    const float* W_cls_u   = (const float*)d_in[3];  // [17, 128]
    const float* W_cls_v   = (const float*)d_in[4];  // [17, 128]
    const float* W_loc     = (const float*)d_in[5];  // [4, 128]
    const float* W_vis     = (const float*)d_in[6];  // [32, 128]
    const float* W_pred    = (const float*)d_in[7];  // [384, 1]
    float* out = (float*)d_out;

    dim3 grid(NN / WARPS_PER_BLOCK, NN / TILE_J);  // (48, 24) = 1152 blocks
    assoc_fused<<<grid, WARPS_PER_BLOCK * 32>>>(vis_maps, locations, kpt_cls,
                                                W_cls_u, W_cls_v, W_loc, W_vis,
                                                W_pred, out);
}

// round 16
// speedup vs baseline: 1.0012x; 1.0012x over previous
#include <cuda_runtime.h>
#include <cuda_bf16.h>
#include <math.h>

#define NN 768
#define NPAIR (NN * NN)          // 589824
#define NJ 17
#define TILE_J 32                // j-tile per block
#define WARPS_PER_BLOCK 16       // 16 i-rows per block (512 threads)
#define NROWS (WARPS_PER_BLOCK + TILE_J)   // 48 vis_feat rows per block

// ---------------- helpers ----------------
__device__ __forceinline__ float4 mul4(float4 a, float4 b) {
    return make_float4(a.x * b.x, a.y * b.y, a.z * b.z, a.w * b.w);
}
__device__ __forceinline__ float dot4(float4 a, float4 b) {
    return fmaf(a.x, b.x, fmaf(a.y, b.y, fmaf(a.z, b.z, a.w * b.w)));
}

// ---------------- single fused kernel ----------------
__global__ void __launch_bounds__(WARPS_PER_BLOCK * 32, 2)
assoc_fused(const float* __restrict__ vm,     // [768, 32]
            const float* __restrict__ loc,    // [768, 5]
            const int*   __restrict__ cls,    // [768]
            const float* __restrict__ Wcu,    // [17, 128]
            const float* __restrict__ Wcv,    // [17, 128]
            const float* __restrict__ Wloc,   // [4, 128]
            const float* __restrict__ Wvis,   // [32, 128]
            const float* __restrict__ Wp,     // [384]
            float* __restrict__ out) {
    __shared__ float sT2[NJ * 128];           // relu(Wcv)
    __shared__ float s_vm[NROWS * 32];        // staged vis_maps rows
    __shared__ float s_vf[NROWS * 128];       // vis_feat rows (16 i then 32 j)
    __shared__ float s_nx[NROWS], s_ny[NROWS];
    __shared__ int   s_cls[NROWS];

    const int t  = threadIdx.x;               // 512
    const int nt = WARPS_PER_BLOCK * 32;
    const int i0 = blockIdx.x * WARPS_PER_BLOCK;
    const int j0 = blockIdx.y * TILE_J;

    // stage vis_maps rows + per-row scalars  (row r<16 -> i0+r, else j0+r-16)
    for (int idx = t; idx < NROWS * 32; idx += nt) {
        const int r = idx >> 5;
        const int g = (r < WARPS_PER_BLOCK) ? (i0 + r) : (j0 + r - WARPS_PER_BLOCK);
        s_vm[idx] = vm[g * 32 + (idx & 31)];
    }
    if (t < NROWS) {
        const int g = (t < WARPS_PER_BLOCK) ? (i0 + t) : (j0 + t - WARPS_PER_BLOCK);
        s_nx[t]  = loc[g * 5 + 3] * (1.0f / 48.0f);
        s_ny[t]  = loc[g * 5 + 4] * (1.0f / 64.0f);
        s_cls[t] = cls[g];
    }
    for (int idx = t; idx < NJ * 128; idx += nt)
        sT2[idx] = fmaxf(Wcv[idx], 0.0f);
    __syncthreads();

    // vis_feat rows: s_vf[r][c] = relu(sum_k s_vm[r][k] * Wvis[k][c])
    for (int idx = t; idx < NROWS * 128; idx += nt) {
        const int r = idx >> 7;
        const int c = idx & 127;
        float acc = 0.0f;
#pragma unroll
        for (int k = 0; k < 32; k++)
            acc = fmaf(s_vm[r * 32 + k], __ldg(&Wvis[k * 128 + c]), acc);
        s_vf[idx] = fmaxf(acc, 0.0f);
    }
    __syncthreads();

    const int warp = t >> 5;
    const int lane = t & 31;
    const int c4 = lane * 4;

    const int i = i0 + warp;

    // i-invariant registers
    const float4 vi  = *reinterpret_cast<const float4*>(&s_vf[warp * 128 + c4]);
    float4 f1 = *reinterpret_cast<const float4*>(&Wcu[s_cls[warp] * 128 + c4]);
    f1.x = fmaxf(f1.x, 0.0f); f1.y = fmaxf(f1.y, 0.0f);
    f1.z = fmaxf(f1.z, 0.0f); f1.w = fmaxf(f1.w, 0.0f);
    const float4 wpv = *reinterpret_cast<const float4*>(&Wp[c4]);
    const float4 wpc = *reinterpret_cast<const float4*>(&Wp[128 + c4]);
    const float4 wpg = *reinterpret_cast<const float4*>(&Wp[256 + c4]);
    const float4 wa  = *reinterpret_cast<const float4*>(&Wloc[c4]);
    const float4 wb  = *reinterpret_cast<const float4*>(&Wloc[128 + c4]);
    const float4 wc  = *reinterpret_cast<const float4*>(&Wloc[256 + c4]);
    const float4 wd  = *reinterpret_cast<const float4*>(&Wloc[384 + c4]);
    const float4 wl0 = make_float4(wa.x + wc.x, wa.y + wc.y, wa.z + wc.z, wa.w + wc.w);
    const float4 wl1 = make_float4(wb.x + wd.x, wb.y + wd.y, wb.z + wd.z, wb.w + wd.w);
    const float  nxi = s_nx[warp];
    const float  nyi = s_ny[warp];

    float* __restrict__ ass = out;                        // [N, N]
    float* frow = out + (size_t)NPAIR + ((size_t)i * NN + j0) * 384;

    for (int jj = 0; jj < TILE_J; jj += 4) {
        float acc4[4];
#pragma unroll
        for (int q = 0; q < 4; q++) {
            const int rj = WARPS_PER_BLOCK + jj + q;
            const float4 vj = *reinterpret_cast<const float4*>(&s_vf[rj * 128 + c4]);
            const float4 f2 = *reinterpret_cast<const float4*>(&sT2[s_cls[rj] * 128 + c4]);
            const float dx = nxi - s_nx[rj];
            const float dy = nyi - s_ny[rj];
            const float g0 = dx * dx;
            const float g1 = dy * dy;

            const float4 v  = mul4(vi, vj);
            const float4 cl = mul4(f1, f2);
            float4 ge;
            ge.x = fmaxf(fmaf(g0, wl0.x, g1 * wl1.x), 0.0f);
            ge.y = fmaxf(fmaf(g0, wl0.y, g1 * wl1.y), 0.0f);
            ge.z = fmaxf(fmaf(g0, wl0.z, g1 * wl1.z), 0.0f);
            ge.w = fmaxf(fmaf(g0, wl0.w, g1 * wl1.w), 0.0f);

            // plain stores (A/B vs __stcs — default L2 policy may write-combine better)
            float* p = frow + (size_t)(jj + q) * 384;
            *reinterpret_cast<float4*>(p + c4)       = v;
            *reinterpret_cast<float4*>(p + 128 + c4) = cl;
            *reinterpret_cast<float4*>(p + 256 + c4) = ge;

            acc4[q] = dot4(v, wpv) + dot4(cl, wpc) + dot4(ge, wpg);
        }

        // two paired reductions: (j, j+1) and (j+2, j+3)
#pragma unroll
        for (int h = 0; h < 2; h++) {
            const bool lo = (lane < 16);
            float comb = (lo ? acc4[2 * h] : acc4[2 * h + 1])
                       + __shfl_xor_sync(0xFFFFFFFFu, lo ? acc4[2 * h + 1] : acc4[2 * h], 16);
#pragma unroll
            for (int off = 8; off; off >>= 1)
                comb += __shfl_xor_sync(0xFFFFFFFFu, comb, off);
            if ((lane & 15) == 0)
                ass[(size_t)i * NN + j0 + jj + 2 * h + (lane >> 4)] =
                    1.0f / (1.0f + __expf(-comb));
        }
    }
}

// ---------------- launch ----------------
extern "C" void kernel_launch(void* const* d_in, const int* in_sizes, int n_in,
                              void* d_out, int out_size) {
    const float* vis_maps  = (const float*)d_in[0];  // [768, 32]
    const float* locations = (const float*)d_in[1];  // [768, 5]
    const int*   kpt_cls   = (const int*)d_in[2];    // [768]
    const float* W_cls_u   = (const float*)d_in[3];  // [17, 128]
    const float* W_cls_v   = (const float*)d_in[4];  // [17, 128]
    const float* W_loc     = (const float*)d_in[5];  // [4, 128]
    const float* W_vis     = (const float*)d_in[6];  // [32, 128]
    const float* W_pred    = (const float*)d_in[7];  // [384, 1]
    float* out = (float*)d_out;

    dim3 grid(NN / WARPS_PER_BLOCK, NN / TILE_J);  // (48, 24) = 1152 blocks
    assoc_fused<<<grid, WARPS_PER_BLOCK * 32>>>(vis_maps, locations, kpt_cls,
                                                W_cls_u, W_cls_v, W_loc, W_vis,
                                                W_pred, out);
}

// round 17
// speedup vs baseline: 1.0556x; 1.0543x over previous
#include <cuda_runtime.h>
#include <cuda_bf16.h>
#include <math.h>

#define NN 768
#define NPAIR (NN * NN)          // 589824
#define NJ 17
#define TILE_J 32                // j-tile per block
#define WARPS_PER_BLOCK 16       // 16 i-rows per block (512 threads)
#define NROWS (WARPS_PER_BLOCK + TILE_J)   // 48 vis_feat rows per block

// ---------------- helpers ----------------
__device__ __forceinline__ float4 mul4(float4 a, float4 b) {
    return make_float4(a.x * b.x, a.y * b.y, a.z * b.z, a.w * b.w);
}
__device__ __forceinline__ float dot4(float4 a, float4 b) {
    return fmaf(a.x, b.x, fmaf(a.y, b.y, fmaf(a.z, b.z, a.w * b.w)));
}

// ---------------- single fused kernel ----------------
__global__ void __launch_bounds__(WARPS_PER_BLOCK * 32, 2)
assoc_fused(const float* __restrict__ vm,     // [768, 32]
            const float* __restrict__ loc,    // [768, 5]
            const int*   __restrict__ cls,    // [768]
            const float* __restrict__ Wcu,    // [17, 128]
            const float* __restrict__ Wcv,    // [17, 128]
            const float* __restrict__ Wloc,   // [4, 128]
            const float* __restrict__ Wvis,   // [32, 128]
            const float* __restrict__ Wp,     // [384]
            float* __restrict__ out) {
    __shared__ float sT2[NJ * 128];           // relu(Wcv)
    __shared__ float s_vm[NROWS * 32];        // staged vis_maps rows
    __shared__ float s_vf[NROWS * 128];       // vis_feat rows (16 i then 32 j)
    __shared__ float s_nx[NROWS], s_ny[NROWS];
    __shared__ int   s_cls[NROWS];

    const int t  = threadIdx.x;               // 512
    const int nt = WARPS_PER_BLOCK * 32;
    // grid swapped: x = j-tile (fast axis), y = i-tile.
    // consecutive block IDs -> contiguous 49 KB j-chunks of the same i rows.
    const int i0 = blockIdx.y * WARPS_PER_BLOCK;
    const int j0 = blockIdx.x * TILE_J;

    // stage vis_maps rows + per-row scalars  (row r<16 -> i0+r, else j0+r-16)
    for (int idx = t; idx < NROWS * 32; idx += nt) {
        const int r = idx >> 5;
        const int g = (r < WARPS_PER_BLOCK) ? (i0 + r) : (j0 + r - WARPS_PER_BLOCK);
        s_vm[idx] = vm[g * 32 + (idx & 31)];
    }
    if (t < NROWS) {
        const int g = (t < WARPS_PER_BLOCK) ? (i0 + t) : (j0 + t - WARPS_PER_BLOCK);
        s_nx[t]  = loc[g * 5 + 3] * (1.0f / 48.0f);
        s_ny[t]  = loc[g * 5 + 4] * (1.0f / 64.0f);
        s_cls[t] = cls[g];
    }
    for (int idx = t; idx < NJ * 128; idx += nt)
        sT2[idx] = fmaxf(Wcv[idx], 0.0f);
    __syncthreads();

    // vis_feat rows: s_vf[r][c] = relu(sum_k s_vm[r][k] * Wvis[k][c])
    for (int idx = t; idx < NROWS * 128; idx += nt) {
        const int r = idx >> 7;
        const int c = idx & 127;
        float acc = 0.0f;
#pragma unroll
        for (int k = 0; k < 32; k++)
            acc = fmaf(s_vm[r * 32 + k], __ldg(&Wvis[k * 128 + c]), acc);
        s_vf[idx] = fmaxf(acc, 0.0f);
    }
    __syncthreads();

    const int warp = t >> 5;
    const int lane = t & 31;
    const int c4 = lane * 4;

    const int i = i0 + warp;

    // i-invariant registers
    const float4 vi  = *reinterpret_cast<const float4*>(&s_vf[warp * 128 + c4]);
    float4 f1 = *reinterpret_cast<const float4*>(&Wcu[s_cls[warp] * 128 + c4]);
    f1.x = fmaxf(f1.x, 0.0f); f1.y = fmaxf(f1.y, 0.0f);
    f1.z = fmaxf(f1.z, 0.0f); f1.w = fmaxf(f1.w, 0.0f);
    const float4 wpv = *reinterpret_cast<const float4*>(&Wp[c4]);
    const float4 wpc = *reinterpret_cast<const float4*>(&Wp[128 + c4]);
    const float4 wpg = *reinterpret_cast<const float4*>(&Wp[256 + c4]);
    const float4 wa  = *reinterpret_cast<const float4*>(&Wloc[c4]);
    const float4 wb  = *reinterpret_cast<const float4*>(&Wloc[128 + c4]);
    const float4 wc  = *reinterpret_cast<const float4*>(&Wloc[256 + c4]);
    const float4 wd  = *reinterpret_cast<const float4*>(&Wloc[384 + c4]);
    const float4 wl0 = make_float4(wa.x + wc.x, wa.y + wc.y, wa.z + wc.z, wa.w + wc.w);
    const float4 wl1 = make_float4(wb.x + wd.x, wb.y + wd.y, wb.z + wd.z, wb.w + wd.w);
    const float  nxi = s_nx[warp];
    const float  nyi = s_ny[warp];

    float* __restrict__ ass = out;                        // [N, N]
    float* frow = out + (size_t)NPAIR + ((size_t)i * NN + j0) * 384;

    for (int jj = 0; jj < TILE_J; jj += 4) {
        float acc4[4];
#pragma unroll
        for (int q = 0; q < 4; q++) {
            const int rj = WARPS_PER_BLOCK + jj + q;
            const float4 vj = *reinterpret_cast<const float4*>(&s_vf[rj * 128 + c4]);
            const float4 f2 = *reinterpret_cast<const float4*>(&sT2[s_cls[rj] * 128 + c4]);
            const float dx = nxi - s_nx[rj];
            const float dy = nyi - s_ny[rj];
            const float g0 = dx * dx;
            const float g1 = dy * dy;

            const float4 v  = mul4(vi, vj);
            const float4 cl = mul4(f1, f2);
            float4 ge;
            ge.x = fmaxf(fmaf(g0, wl0.x, g1 * wl1.x), 0.0f);
            ge.y = fmaxf(fmaf(g0, wl0.y, g1 * wl1.y), 0.0f);
            ge.z = fmaxf(fmaf(g0, wl0.z, g1 * wl1.z), 0.0f);
            ge.w = fmaxf(fmaf(g0, wl0.w, g1 * wl1.w), 0.0f);

            float* p = frow + (size_t)(jj + q) * 384;
            __stcs(reinterpret_cast<float4*>(p + c4),       v);
            __stcs(reinterpret_cast<float4*>(p + 128 + c4), cl);
            __stcs(reinterpret_cast<float4*>(p + 256 + c4), ge);

            acc4[q] = dot4(v, wpv) + dot4(cl, wpc) + dot4(ge, wpg);
        }

        // two paired reductions: (j, j+1) and (j+2, j+3)
#pragma unroll
        for (int h = 0; h < 2; h++) {
            const bool lo = (lane < 16);
            float comb = (lo ? acc4[2 * h] : acc4[2 * h + 1])
                       + __shfl_xor_sync(0xFFFFFFFFu, lo ? acc4[2 * h + 1] : acc4[2 * h], 16);
#pragma unroll
            for (int off = 8; off; off >>= 1)
                comb += __shfl_xor_sync(0xFFFFFFFFu, comb, off);
            if ((lane & 15) == 0)
                __stcs(&ass[(size_t)i * NN + j0 + jj + 2 * h + (lane >> 4)],
                       1.0f / (1.0f + __expf(-comb)));
        }
    }
}

// ---------------- launch ----------------
extern "C" void kernel_launch(void* const* d_in, const int* in_sizes, int n_in,
                              void* d_out, int out_size) {
    const float* vis_maps  = (const float*)d_in[0];  // [768, 32]
    const float* locations = (const float*)d_in[1];  // [768, 5]
    const int*   kpt_cls   = (const int*)d_in[2];    // [768]
    const float* W_cls_u   = (const float*)d_in[3];  // [17, 128]
    const float* W_cls_v   = (const float*)d_in[4];  // [17, 128]
    const float* W_loc     = (const float*)d_in[5];  // [4, 128]
    const float* W_vis     = (const float*)d_in[6];  // [32, 128]
    const float* W_pred    = (const float*)d_in[7];  // [384, 1]
    float* out = (float*)d_out;

    dim3 grid(NN / TILE_J, NN / WARPS_PER_BLOCK);  // (24, 48) — x = j-tile
    assoc_fused<<<grid, WARPS_PER_BLOCK * 32>>>(vis_maps, locations, kpt_cls,
                                                W_cls_u, W_cls_v, W_loc, W_vis,
                                                W_pred, out);
}